// round 16
// baseline (speedup 1.0000x reference)
#include <cuda_runtime.h>
#include <cuda_bf16.h>
#include <cuda_fp16.h>
#include <stdint.h>
#include <math.h>

#define BATCH 8
#define CH    128
#define NPIX  4096
#define BR    128
#define BC    64
#define NT    (NPIX / BC)   // 64
#define JSPLIT 4
#define TILES_PER_UNIT (NT / JSPLIT)   // 16

// bf16 hi/lo split operands (S-phase emulated-fp32 MMA)
__device__ __align__(16) __nv_bfloat16 g_Qhi[BATCH * NPIX * CH];  // [b][n][c]
__device__ __align__(16) __nv_bfloat16 g_Qlo[BATCH * NPIX * CH];
__device__ __align__(16) __nv_bfloat16 g_Khi[BATCH * NPIX * CH];  // [b][n][c]
__device__ __align__(16) __nv_bfloat16 g_Klo[BATCH * NPIX * CH];
// V in fp16 (PV is single-term fp16 MMA)
__device__ __align__(16) __half g_Vh[BATCH * CH * NPIX];          // [b][c][n]

// split-j partials: O [b][jc][iblk][i 128][c 128]; ML [unit][2][128] (m, l)
__device__ __align__(16) float g_O[BATCH * JSPLIT * 32 * 128 * 128];  // 64 MB
__device__ __align__(16) float g_ML[BATCH * JSPLIT * 32 * 256];

typedef unsigned long long u64;

__device__ __forceinline__ uint32_t smem_u32(const void* p) {
    uint32_t a;
    asm("{ .reg .u64 t; cvta.to.shared.u64 t, %1; cvt.u32.u64 %0, t; }" : "=r"(a) : "l"(p));
    return a;
}
__device__ __forceinline__ void cpasync16(uint32_t dst, const void* src) {
    asm volatile("cp.async.cg.shared.global [%0], [%1], 16;" :: "r"(dst), "l"(src));
}
#define CP_COMMIT() asm volatile("cp.async.commit_group;" ::: "memory")
#define CP_WAIT0()  asm volatile("cp.async.wait_group 0;" ::: "memory")

__device__ __forceinline__ float ex2(float x) {
    float y; asm("ex2.approx.ftz.f32 %0, %1;" : "=f"(y) : "f"(x)); return y;
}

// m16n8k16 row.col bf16 -> fp32, D==C in place
__device__ __forceinline__ void mma16816(float* c,
    uint32_t a0, uint32_t a1, uint32_t a2, uint32_t a3, uint32_t b0, uint32_t b1) {
    asm volatile(
        "mma.sync.aligned.m16n8k16.row.col.f32.bf16.bf16.f32 "
        "{%0,%1,%2,%3}, {%4,%5,%6,%7}, {%8,%9}, {%0,%1,%2,%3};"
        : "+f"(c[0]), "+f"(c[1]), "+f"(c[2]), "+f"(c[3])
        : "r"(a0), "r"(a1), "r"(a2), "r"(a3), "r"(b0), "r"(b1));
}
// fp16 variant
__device__ __forceinline__ void mma16816h(float* c,
    uint32_t a0, uint32_t a1, uint32_t a2, uint32_t a3, uint32_t b0, uint32_t b1) {
    asm volatile(
        "mma.sync.aligned.m16n8k16.row.col.f32.f16.f16.f32 "
        "{%0,%1,%2,%3}, {%4,%5,%6,%7}, {%8,%9}, {%0,%1,%2,%3};"
        : "+f"(c[0]), "+f"(c[1]), "+f"(c[2]), "+f"(c[3])
        : "r"(a0), "r"(a1), "r"(a2), "r"(a3), "r"(b0), "r"(b1));
}

__device__ __forceinline__ void ldsm4(uint32_t& r0, uint32_t& r1, uint32_t& r2,
                                      uint32_t& r3, uint32_t addr) {
    asm volatile("ldmatrix.sync.aligned.m8n8.x4.shared.b16 {%0,%1,%2,%3}, [%4];"
                 : "=r"(r0), "=r"(r1), "=r"(r2), "=r"(r3) : "r"(addr));
}
__device__ __forceinline__ void ldsm4t(uint32_t& r0, uint32_t& r1, uint32_t& r2,
                                       uint32_t& r3, uint32_t addr) {
    asm volatile("ldmatrix.sync.aligned.m8n8.x4.trans.shared.b16 {%0,%1,%2,%3}, [%4];"
                 : "=r"(r0), "=r"(r1), "=r"(r2), "=r"(r3) : "r"(addr));
}

__device__ __forceinline__ uint32_t f16pack(float pe, float po) {
    uint32_t r;
    asm("cvt.rn.f16x2.f32 %0, %1, %2;" : "=r"(r) : "f"(po), "f"(pe));
    return r;
}
__device__ __forceinline__ void split2(float a, float b, uint32_t& hi, uint32_t& lo) {
    __nv_bfloat162 h = __floats2bfloat162_rn(a, b);
    float2 hf = __bfloat1622float2(h);
    __nv_bfloat162 l = __floats2bfloat162_rn(a - hf.x, b - hf.y);
    union { __nv_bfloat162 v; uint32_t u; } ch, cl;
    ch.v = h; cl.v = l;
    hi = ch.u; lo = cl.u;
}

#define LOG2E 1.4426950408889634f

// ====== QKV projection on HMMA bf16x3 ======
// grid (32, 2, 8): y==0 -> Q (swapped orient); y==1 -> K (swapped) + V (normal)
// smem: W1hi | W1lo | W2hi | W2lo | Xhi | Xlo  (each 34816 B, rows 272 B)
#define W1HI_B 0
#define W1LO_B 34816
#define W2HI_B 69632
#define W2LO_B 104448
#define XHI_B  139264
#define XLO_B  174080
#define PROJ_SMEM_BYTES 208896

__device__ __forceinline__ void stageW(char* smc, int t, const float* __restrict__ W,
                                       int hiB, int loB) {
#pragma unroll
    for (int r = 0; r < 4; ++r) {
        int task = t + 256 * r;            // 1024 tasks, each 16 c-values
        int o = task >> 3, c16 = (task & 7) * 16;
        const float4* ws = (const float4*)&W[o * CH + c16];
        uint32_t hi[8], lo[8];
#pragma unroll
        for (int j = 0; j < 4; ++j) {
            float4 w4 = ws[j];
            split2(w4.x, w4.y, hi[2 * j], lo[2 * j]);
            split2(w4.z, w4.w, hi[2 * j + 1], lo[2 * j + 1]);
        }
        char* dh = smc + hiB + o * 272 + c16 * 2;
        char* dl = smc + loB + o * 272 + c16 * 2;
        ((uint4*)dh)[0] = make_uint4(hi[0], hi[1], hi[2], hi[3]);
        ((uint4*)dh)[1] = make_uint4(hi[4], hi[5], hi[6], hi[7]);
        ((uint4*)dl)[0] = make_uint4(lo[0], lo[1], lo[2], lo[3]);
        ((uint4*)dl)[1] = make_uint4(lo[4], lo[5], lo[6], lo[7]);
    }
}

__global__ void __launch_bounds__(256, 1) qkv_kernel(
    const float* __restrict__ x1, const float* __restrict__ x2,
    const float* __restrict__ Wq, const float* __restrict__ bq,
    const float* __restrict__ Wk, const float* __restrict__ bk,
    const float* __restrict__ Wv, const float* __restrict__ bv)
{
    extern __shared__ __align__(16) char smc[];
    const uint32_t sb = smem_u32(smc);

    const int t = threadIdx.x;
    const int wid = t >> 5;
    const int lane = t & 31;
    const int l7 = lane & 7;
    const int r8 = lane >> 3;
    const bool isQ = (blockIdx.y == 0);
    const int b = blockIdx.z, p0 = blockIdx.x * 128;

    const float* X = (isQ ? x1 : x2) + (size_t)b * CH * NPIX;

    // ---- stage X tile hi/lo: [c][p+pad] bf16 ----
#pragma unroll
    for (int r = 0; r < 16; ++r) {
        int idx = t + 256 * r;
        int c = idx >> 5, p4 = (idx & 31) * 4;
        float4 x4 = *(const float4*)&X[(size_t)c * NPIX + p0 + p4];
        uint32_t h0, l0, h1, l1;
        split2(x4.x, x4.y, h0, l0);
        split2(x4.z, x4.w, h1, l1);
        *(uint2*)(smc + XHI_B + c * 272 + p4 * 2) = make_uint2(h0, h1);
        *(uint2*)(smc + XLO_B + c * 272 + p4 * 2) = make_uint2(l0, l1);
    }
    // ---- stage weights (all upfront; single sync) ----
    stageW(smc, t, isQ ? Wq : Wk, W1HI_B, W1LO_B);
    if (!isQ) stageW(smc, t, Wv, W2HI_B, W2LO_B);
    __syncthreads();

    const int g = lane >> 2, q4 = lane & 3;

    // ==== GEMM 1: Q or K, swapped Out^T[p][o]; A = X (trans), B = W1 ====
    {
        const float* bias = isQ ? bq : bk;
        float acc[16][4];
#pragma unroll
        for (int n = 0; n < 16; ++n)
#pragma unroll
            for (int r = 0; r < 4; ++r) acc[n][r] = 0.f;

        const uint32_t aT = sb + XHI_B
            + (uint32_t)((r8 & 1) * 8 + l7) * 272
            + (uint32_t)(wid * 16 + (r8 >> 1) * 8) * 2;
        const uint32_t bW = sb + W1HI_B
            + (uint32_t)((r8 >> 1) * 8 + l7) * 272 + (uint32_t)(r8 & 1) * 16;
#pragma unroll
        for (int kk = 0; kk < 8; ++kk) {
            uint32_t a0h, a1h, a2h, a3h, a0l, a1l, a2l, a3l;
            ldsm4t(a0h, a2h, a1h, a3h, aT + kk * 16 * 272);
            ldsm4t(a0l, a2l, a1l, a3l, aT + (XLO_B - XHI_B) + kk * 16 * 272);
#pragma unroll
            for (int np = 0; np < 8; ++np) {
                uint32_t b00, b01, b10, b11, c00, c01, c10, c11;
                ldsm4(b00, b01, b10, b11, bW + np * 4352 + kk * 32);
                ldsm4(c00, c01, c10, c11, bW + (W1LO_B - W1HI_B) + np * 4352 + kk * 32);
                mma16816(acc[2 * np],     a0h, a1h, a2h, a3h, b00, b01);
                mma16816(acc[2 * np],     a0l, a1l, a2l, a3l, b00, b01);
                mma16816(acc[2 * np],     a0h, a1h, a2h, a3h, c00, c01);
                mma16816(acc[2 * np + 1], a0h, a1h, a2h, a3h, b10, b11);
                mma16816(acc[2 * np + 1], a0l, a1l, a2l, a3l, b10, b11);
                mma16816(acc[2 * np + 1], a0h, a1h, a2h, a3h, c10, c11);
            }
        }
        const float qsc = isQ ? LOG2E : 1.0f;
        __nv_bfloat16* dHi = isQ ? g_Qhi : g_Khi;
        __nv_bfloat16* dLo = isQ ? g_Qlo : g_Klo;
        const int p = wid * 16 + g;
        size_t r0 = ((size_t)b * NPIX + p0 + p) * CH;
        size_t r8b = r0 + (size_t)8 * CH;
#pragma unroll
        for (int n = 0; n < 16; ++n) {
            const int o = n * 8 + 2 * q4;
            float2 bo = *(const float2*)&bias[o];
            uint32_t h0, l0, h1, l1;
            split2((acc[n][0] + bo.x) * qsc, (acc[n][1] + bo.y) * qsc, h0, l0);
            split2((acc[n][2] + bo.x) * qsc, (acc[n][3] + bo.y) * qsc, h1, l1);
            *(uint32_t*)(dHi + r0 + o)  = h0;
            *(uint32_t*)(dLo + r0 + o)  = l0;
            *(uint32_t*)(dHi + r8b + o) = h1;
            *(uint32_t*)(dLo + r8b + o) = l1;
        }
    }

    // ==== GEMM 2 (KV CTA only): V normal Out[o][p]; A = W2, B = X (trans) ====
    if (!isQ) {
        float acc[16][4];
#pragma unroll
        for (int n = 0; n < 16; ++n)
#pragma unroll
            for (int r = 0; r < 4; ++r) acc[n][r] = 0.f;

        const uint32_t aH = sb + W2HI_B
            + (uint32_t)(wid * 16 + l7 + (r8 & 1) * 8) * 272
            + (uint32_t)((lane >> 4) & 1) * 16;
        const uint32_t aL = aH + (W2LO_B - W2HI_B);
        const uint32_t bT = sb + XHI_B
            + (uint32_t)((r8 & 1) * 8 + l7) * 272 + (uint32_t)(r8 >> 1) * 16;
#pragma unroll
        for (int kk = 0; kk < 8; ++kk) {
            uint32_t a0h, a1h, a2h, a3h, a0l, a1l, a2l, a3l;
            ldsm4(a0h, a1h, a2h, a3h, aH + kk * 32);
            ldsm4(a0l, a1l, a2l, a3l, aL + kk * 32);
            const uint32_t bk16 = bT + (uint32_t)kk * 16 * 272;
#pragma unroll
            for (int np = 0; np < 8; ++np) {
                uint32_t b00, b01, b10, b11, c00, c01, c10, c11;
                ldsm4t(b00, b01, b10, b11, bk16 + np * 32);
                ldsm4t(c00, c01, c10, c11, bk16 + (XLO_B - XHI_B) + np * 32);
                mma16816(acc[2 * np],     a0h, a1h, a2h, a3h, b00, b01);
                mma16816(acc[2 * np],     a0l, a1l, a2l, a3l, b00, b01);
                mma16816(acc[2 * np],     a0h, a1h, a2h, a3h, c00, c01);
                mma16816(acc[2 * np + 1], a0h, a1h, a2h, a3h, b10, b11);
                mma16816(acc[2 * np + 1], a0l, a1l, a2l, a3l, b10, b11);
                mma16816(acc[2 * np + 1], a0h, a1h, a2h, a3h, c10, c11);
            }
        }
        const int o0 = wid * 16 + g;
        float bo0 = bv[o0], bo8 = bv[o0 + 8];
        size_t rb0 = ((size_t)b * CH + o0) * NPIX + p0;
        size_t rb8 = rb0 + (size_t)8 * NPIX;
#pragma unroll
        for (int n = 0; n < 16; ++n) {
            const int p = n * 8 + 2 * q4;
            *(uint32_t*)(g_Vh + rb0 + p) = f16pack(acc[n][0] + bo0, acc[n][1] + bo0);
            *(uint32_t*)(g_Vh + rb8 + p) = f16pack(acc[n][2] + bo8, acc[n][3] + bo8);
        }
    }
}

// ==== flash attention partial: bf16x3 S + fp16 PV with running row-max ====
#define QHI_B 0
#define QLO_B 34816
#define BUF_B 69632
#define BUFSTRIDE 53248   // Khi 17408 + Klo 17408 + Vh 18432
#define KHI_B(d) (BUF_B + (d) * BUFSTRIDE)
#define VH_B(d)  (KHI_B(d) + 2 * 17408)
#define ATTN_SMEM_BYTES (BUF_B + 2 * BUFSTRIDE)   // 176128

__global__ void __launch_bounds__(256, 1) attn_kernel()
{
    extern __shared__ __align__(16) uint32_t sm32[];
    const uint32_t sb = smem_u32(sm32);

    const int t = threadIdx.x;
    const int wid = t >> 5;
    const int lane = t & 31;
    const int l7 = lane & 7;
    const int r8 = lane >> 3;
    const int iblk = blockIdx.x;
    const int jc   = blockIdx.y;
    const int b    = blockIdx.z;
    const int i0 = iblk * BR;
    const int jt0 = jc * TILES_PER_UNIT;

    {
        const char* qh = (const char*)(g_Qhi + ((size_t)b * NPIX + i0) * CH);
        const char* ql = (const char*)(g_Qlo + ((size_t)b * NPIX + i0) * CH);
#pragma unroll
        for (int r = 0; r < 8; ++r) {
            int idx = t + 256 * r;
            int row = idx >> 4, off = idx & 15;
            cpasync16(sb + QHI_B + row * 272 + off * 16, qh + (size_t)idx * 16);
            cpasync16(sb + QLO_B + row * 272 + off * 16, ql + (size_t)idx * 16);
        }
        const int j0 = jt0 * BC;
        const char* kh = (const char*)(g_Khi + ((size_t)b * NPIX + j0) * CH);
        const char* kl = (const char*)(g_Klo + ((size_t)b * NPIX + j0) * CH);
        const char* vh = (const char*)(g_Vh + (size_t)b * CH * NPIX + j0);
#pragma unroll
        for (int r = 0; r < 4; ++r) {
            int idx = t + 256 * r;
            int row = idx >> 4, off = idx & 15;
            cpasync16(sb + KHI_B(0) + row * 272 + off * 16, kh + (size_t)idx * 16);
            cpasync16(sb + KHI_B(0) + 17408 + row * 272 + off * 16, kl + (size_t)idx * 16);
        }
#pragma unroll
        for (int r = 0; r < 4; ++r) {
            int idx = t + 256 * r;
            int row = idx >> 3, off = idx & 7;
            cpasync16(sb + VH_B(0) + row * 144 + off * 16,
                      vh + (size_t)row * NPIX * 2 + off * 16);
        }
        CP_COMMIT();
    }

    float o[16][4];
#pragma unroll
    for (int n = 0; n < 16; ++n)
#pragma unroll
        for (int r = 0; r < 4; ++r) o[n][r] = 0.f;
    float lsum0 = 0.f, lsum1 = 0.f;
    float m0 = -INFINITY, m1 = -INFINITY;

    const uint32_t aOffH = sb + QHI_B
        + (uint32_t)(wid * 16 + l7 + (r8 & 1) * 8) * 272 + (uint32_t)((lane >> 4) & 1) * 16;
    const uint32_t aOffL = aOffH + (QLO_B - QHI_B);
    const uint32_t bRow = (uint32_t)((r8 >> 1) * 8 + l7);
    const uint32_t bOffK = bRow * 272 + (uint32_t)(r8 & 1) * 16;
    const uint32_t bOffV = bRow * 144 + (uint32_t)(r8 & 1) * 16;

    for (int jt = jt0; jt < jt0 + TILES_PER_UNIT; ++jt) {
        const int d = jt & 1;
        CP_WAIT0();
        __syncthreads();

        if (jt + 1 < jt0 + TILES_PER_UNIT) {
            const int j0n = (jt + 1) * BC, dn = (jt + 1) & 1;
            const char* kh = (const char*)(g_Khi + ((size_t)b * NPIX + j0n) * CH);
            const char* kl = (const char*)(g_Klo + ((size_t)b * NPIX + j0n) * CH);
            const char* vh = (const char*)(g_Vh + (size_t)b * CH * NPIX + j0n);
#pragma unroll
            for (int r = 0; r < 4; ++r) {
                int idx = t + 256 * r;
                int row = idx >> 4, off = idx & 15;
                cpasync16(sb + KHI_B(dn) + row * 272 + off * 16, kh + (size_t)idx * 16);
                cpasync16(sb + KHI_B(dn) + 17408 + row * 272 + off * 16, kl + (size_t)idx * 16);
            }
#pragma unroll
            for (int r = 0; r < 4; ++r) {
                int idx = t + 256 * r;
                int row = idx >> 3, off = idx & 7;
                cpasync16(sb + VH_B(dn) + row * 144 + off * 16,
                          vh + (size_t)row * NPIX * 2 + off * 16);
            }
            CP_COMMIT();
        }

        // ---- S = Q K^T (3-term bf16) ----
        float s[8][4];
#pragma unroll
        for (int n = 0; n < 8; ++n)
#pragma unroll
            for (int r = 0; r < 4; ++r) s[n][r] = 0.f;

        const uint32_t kBase = sb + KHI_B(d) + bOffK;
#pragma unroll
        for (int kk = 0; kk < 8; ++kk) {
            uint32_t a0h, a1h, a2h, a3h, a0l, a1l, a2l, a3l;
            ldsm4(a0h, a1h, a2h, a3h, aOffH + kk * 32);
            ldsm4(a0l, a1l, a2l, a3l, aOffL + kk * 32);
#pragma unroll
            for (int np = 0; np < 4; ++np) {
                uint32_t b00, b01, b10, b11, c00, c01, c10, c11;
                ldsm4(b00, b01, b10, b11, kBase + np * 4352 + kk * 32);
                ldsm4(c00, c01, c10, c11, kBase + 17408 + np * 4352 + kk * 32);
                mma16816(s[2 * np],     a0h, a1h, a2h, a3h, b00, b01);
                mma16816(s[2 * np],     a0l, a1l, a2l, a3l, b00, b01);
                mma16816(s[2 * np],     a0h, a1h, a2h, a3h, c00, c01);
                mma16816(s[2 * np + 1], a0h, a1h, a2h, a3h, b10, b11);
                mma16816(s[2 * np + 1], a0l, a1l, a2l, a3l, b10, b11);
                mma16816(s[2 * np + 1], a0h, a1h, a2h, a3h, c10, c11);
            }
        }

        // ---- running row-max, guarded rescale, exp2, sums ----
        {
            float mx0 = s[0][0], mx1 = s[0][2];
#pragma unroll
            for (int n = 0; n < 8; ++n) {
                mx0 = fmaxf(mx0, fmaxf(s[n][0], s[n][1]));
                mx1 = fmaxf(mx1, fmaxf(s[n][2], s[n][3]));
            }
            mx0 = fmaxf(mx0, __shfl_xor_sync(0xffffffffu, mx0, 1));
            mx0 = fmaxf(mx0, __shfl_xor_sync(0xffffffffu, mx0, 2));
            mx1 = fmaxf(mx1, __shfl_xor_sync(0xffffffffu, mx1, 1));
            mx1 = fmaxf(mx1, __shfl_xor_sync(0xffffffffu, mx1, 2));
            float m0n = fmaxf(m0, mx0), m1n = fmaxf(m1, mx1);
            float sc0 = ex2(m0 - m0n), sc1 = ex2(m1 - m1n);
            m0 = m0n; m1 = m1n;
            lsum0 *= sc0; lsum1 *= sc1;
#pragma unroll
            for (int n = 0; n < 8; ++n) {
                s[n][0] = ex2(s[n][0] - m0n);
                s[n][1] = ex2(s[n][1] - m0n);
                s[n][2] = ex2(s[n][2] - m1n);
                s[n][3] = ex2(s[n][3] - m1n);
                lsum0 += s[n][0] + s[n][1];
                lsum1 += s[n][2] + s[n][3];
            }
            if (sc0 < 1.f || sc1 < 1.f) {   // skipped once the max settles
#pragma unroll
                for (int n = 0; n < 16; ++n) {
                    o[n][0] *= sc0; o[n][1] *= sc0;
                    o[n][2] *= sc1; o[n][3] *= sc1;
                }
            }
        }

        // ---- O += P V : single-term fp16 ----
        const uint32_t vBase = sb + VH_B(d) + bOffV;
#pragma unroll
        for (int kk = 0; kk < 4; ++kk) {
            uint32_t pa0 = f16pack(s[2 * kk][0],     s[2 * kk][1]);
            uint32_t pa1 = f16pack(s[2 * kk][2],     s[2 * kk][3]);
            uint32_t pa2 = f16pack(s[2 * kk + 1][0], s[2 * kk + 1][1]);
            uint32_t pa3 = f16pack(s[2 * kk + 1][2], s[2 * kk + 1][3]);
#pragma unroll
            for (int n2 = 0; n2 < 8; ++n2) {
                uint32_t b00, b01, b10, b11;
                ldsm4(b00, b01, b10, b11, vBase + n2 * 2304 + kk * 32);
                mma16816h(o[2 * n2],     pa0, pa1, pa2, pa3, b00, b01);
                mma16816h(o[2 * n2 + 1], pa0, pa1, pa2, pa3, b10, b11);
            }
        }
        __syncthreads();
    }

    lsum0 += __shfl_xor_sync(0xffffffffu, lsum0, 1);
    lsum0 += __shfl_xor_sync(0xffffffffu, lsum0, 2);
    lsum1 += __shfl_xor_sync(0xffffffffu, lsum1, 1);
    lsum1 += __shfl_xor_sync(0xffffffffu, lsum1, 2);

    const size_t unit = ((size_t)(b * JSPLIT + jc) * 32 + iblk);
    float* Ob = g_O + unit * (128 * 128);
    float* ML = g_ML + unit * 256;
    const int g = lane >> 2, q = lane & 3;
    const int i = wid * 16 + g;
    if ((lane & 3) == 0) {
        ML[i]           = m0;
        ML[i + 8]       = m1;
        ML[128 + i]     = lsum0;
        ML[128 + i + 8] = lsum1;
    }
#pragma unroll
    for (int n = 0; n < 16; ++n) {
        const int c = n * 8 + 2 * q;
        *(float2*)&Ob[(size_t)i * 128 + c]       = make_float2(o[n][0], o[n][1]);
        *(float2*)&Ob[(size_t)(i + 8) * 128 + c] = make_float2(o[n][2], o[n][3]);
    }
}

// ==== merge: max-combine 4 j-chunk partials, normalize, transpose, store ====
#define MERGE_SMEM_BYTES (128 * 129 * 4 + 128 * 4 + 4 * 128 * 4)   // 68608

__global__ void __launch_bounds__(256, 1) merge_kernel(float* __restrict__ out)
{
    extern __shared__ __align__(16) float ms[];
    float* Os   = ms;                       // [c:128][i:129]
    float* Linv = ms + 128 * 129;           // [128]
    float* F    = ms + 128 * 129 + 128;     // [4][128]

    const int t = threadIdx.x;
    const int iblk = blockIdx.x;
    const int b    = blockIdx.y;

    const float* O0 = g_O + ((size_t)(b * JSPLIT) * 32 + iblk) * (128 * 128);
    const size_t sj = (size_t)32 * 128 * 128;

    if (t < 128) {
        const size_t u0 = ((size_t)(b * JSPLIT) * 32 + iblk) * 256;
        const size_t uj = (size_t)32 * 256;
        float m[4], l[4];
#pragma unroll
        for (int c = 0; c < 4; ++c) {
            m[c] = g_ML[u0 + c * uj + t];
            l[c] = g_ML[u0 + c * uj + 128 + t];
        }
        float M = fmaxf(fmaxf(m[0], m[1]), fmaxf(m[2], m[3]));
        float L = 0.f;
#pragma unroll
        for (int c = 0; c < 4; ++c) {
            float f = ex2(m[c] - M);
            F[c * 128 + t] = f;
            L += l[c] * f;
        }
        Linv[t] = 1.f / L;
    }
    __syncthreads();

#pragma unroll
    for (int r = 0; r < 16; ++r) {
        int idx = (r * 256 + t) * 4;
        int i = idx >> 7, c = idx & 127;
        float f0 = F[i], f1 = F[128 + i], f2 = F[256 + i], f3 = F[384 + i];
        float4 a  = *(const float4*)&O0[idx];
        float4 b2 = *(const float4*)&O0[sj + idx];
        float4 c4 = *(const float4*)&O0[2 * sj + idx];
        float4 d4 = *(const float4*)&O0[3 * sj + idx];
        Os[(c + 0) * 129 + i] = a.x * f0 + b2.x * f1 + c4.x * f2 + d4.x * f3;
        Os[(c + 1) * 129 + i] = a.y * f0 + b2.y * f1 + c4.y * f2 + d4.y * f3;
        Os[(c + 2) * 129 + i] = a.z * f0 + b2.z * f1 + c4.z * f2 + d4.z * f3;
        Os[(c + 3) * 129 + i] = a.w * f0 + b2.w * f1 + c4.w * f2 + d4.w * f3;
    }
    __syncthreads();

    const int c = t >> 1, h = t & 1;
    const float* src = Os + c * 129 + 64 * h;
    const float* li  = Linv + 64 * h;
    float* dst = out + ((size_t)b * CH + c) * NPIX + iblk * 128 + 64 * h;
#pragma unroll
    for (int k = 0; k < 16; ++k) {
        ((float4*)dst)[k] = make_float4(src[4 * k]     * li[4 * k],
                                        src[4 * k + 1] * li[4 * k + 1],
                                        src[4 * k + 2] * li[4 * k + 2],
                                        src[4 * k + 3] * li[4 * k + 3]);
    }
}

// ============================================================
extern "C" void kernel_launch(void* const* d_in, const int* in_sizes, int n_in,
                              void* d_out, int out_size)
{
    (void)in_sizes; (void)n_in; (void)out_size;
    const float* x1 = (const float*)d_in[0];
    const float* x2 = (const float*)d_in[1];
    const float* Wq = (const float*)d_in[2];
    const float* bq = (const float*)d_in[3];
    const float* Wk = (const float*)d_in[4];
    const float* bk = (const float*)d_in[5];
    const float* Wv = (const float*)d_in[6];
    const float* bv = (const float*)d_in[7];
    float* out = (float*)d_out;

    cudaFuncSetAttribute(qkv_kernel, cudaFuncAttributeMaxDynamicSharedMemorySize, PROJ_SMEM_BYTES);
    cudaFuncSetAttribute(attn_kernel, cudaFuncAttributeMaxDynamicSharedMemorySize, ATTN_SMEM_BYTES);
    cudaFuncSetAttribute(merge_kernel, cudaFuncAttributeMaxDynamicSharedMemorySize, MERGE_SMEM_BYTES);

    qkv_kernel<<<dim3(NPIX / 128, 2, BATCH), 256, PROJ_SMEM_BYTES>>>(x1, x2, Wq, bq, Wk, bk, Wv, bv);
    attn_kernel<<<dim3(NPIX / BR, JSPLIT, BATCH), 256, ATTN_SMEM_BYTES>>>();
    merge_kernel<<<dim3(NPIX / 128, BATCH), 256, MERGE_SMEM_BYTES>>>(out);
}

// round 17
// speedup vs baseline: 1.5907x; 1.5907x over previous
#include <cuda_runtime.h>
#include <cuda_bf16.h>
#include <cuda_fp16.h>
#include <stdint.h>
#include <math.h>

#define BATCH 8
#define CH    128
#define NPIX  4096
#define BR    128
#define BC    64
#define NT    (NPIX / BC)   // 64
#define JSPLIT 4
#define TILES_PER_UNIT (NT / JSPLIT)   // 16

// bf16 hi/lo split operands (S-phase emulated-fp32 MMA)
__device__ __align__(16) __nv_bfloat16 g_Qhi[BATCH * NPIX * CH];  // [b][n][c]
__device__ __align__(16) __nv_bfloat16 g_Qlo[BATCH * NPIX * CH];
__device__ __align__(16) __nv_bfloat16 g_Khi[BATCH * NPIX * CH];  // [b][n][c]
__device__ __align__(16) __nv_bfloat16 g_Klo[BATCH * NPIX * CH];
// V in fp16 (PV is single-term fp16 MMA)
__device__ __align__(16) __half g_Vh[BATCH * CH * NPIX];          // [b][c][n]

// split-j partials: O [b][jc][iblk][i 128][c 128]; ML [unit][2][128] (m, l)
__device__ __align__(16) float g_O[BATCH * JSPLIT * 32 * 128 * 128];  // 64 MB
__device__ __align__(16) float g_ML[BATCH * JSPLIT * 32 * 256];

typedef unsigned long long u64;

__device__ __forceinline__ uint32_t smem_u32(const void* p) {
    uint32_t a;
    asm("{ .reg .u64 t; cvta.to.shared.u64 t, %1; cvt.u32.u64 %0, t; }" : "=r"(a) : "l"(p));
    return a;
}
__device__ __forceinline__ void cpasync16(uint32_t dst, const void* src) {
    asm volatile("cp.async.cg.shared.global [%0], [%1], 16;" :: "r"(dst), "l"(src));
}
#define CP_COMMIT() asm volatile("cp.async.commit_group;" ::: "memory")
#define CP_WAIT0()  asm volatile("cp.async.wait_group 0;" ::: "memory")

__device__ __forceinline__ float ex2(float x) {
    float y; asm("ex2.approx.ftz.f32 %0, %1;" : "=f"(y) : "f"(x)); return y;
}

// m16n8k16 row.col bf16 -> fp32, D==C in place
__device__ __forceinline__ void mma16816(float* c,
    uint32_t a0, uint32_t a1, uint32_t a2, uint32_t a3, uint32_t b0, uint32_t b1) {
    asm volatile(
        "mma.sync.aligned.m16n8k16.row.col.f32.bf16.bf16.f32 "
        "{%0,%1,%2,%3}, {%4,%5,%6,%7}, {%8,%9}, {%0,%1,%2,%3};"
        : "+f"(c[0]), "+f"(c[1]), "+f"(c[2]), "+f"(c[3])
        : "r"(a0), "r"(a1), "r"(a2), "r"(a3), "r"(b0), "r"(b1));
}
// fp16 variant
__device__ __forceinline__ void mma16816h(float* c,
    uint32_t a0, uint32_t a1, uint32_t a2, uint32_t a3, uint32_t b0, uint32_t b1) {
    asm volatile(
        "mma.sync.aligned.m16n8k16.row.col.f32.f16.f16.f32 "
        "{%0,%1,%2,%3}, {%4,%5,%6,%7}, {%8,%9}, {%0,%1,%2,%3};"
        : "+f"(c[0]), "+f"(c[1]), "+f"(c[2]), "+f"(c[3])
        : "r"(a0), "r"(a1), "r"(a2), "r"(a3), "r"(b0), "r"(b1));
}

__device__ __forceinline__ void ldsm4(uint32_t& r0, uint32_t& r1, uint32_t& r2,
                                      uint32_t& r3, uint32_t addr) {
    asm volatile("ldmatrix.sync.aligned.m8n8.x4.shared.b16 {%0,%1,%2,%3}, [%4];"
                 : "=r"(r0), "=r"(r1), "=r"(r2), "=r"(r3) : "r"(addr));
}
__device__ __forceinline__ void ldsm4t(uint32_t& r0, uint32_t& r1, uint32_t& r2,
                                       uint32_t& r3, uint32_t addr) {
    asm volatile("ldmatrix.sync.aligned.m8n8.x4.trans.shared.b16 {%0,%1,%2,%3}, [%4];"
                 : "=r"(r0), "=r"(r1), "=r"(r2), "=r"(r3) : "r"(addr));
}

__device__ __forceinline__ uint32_t f16pack(float pe, float po) {
    uint32_t r;
    asm("cvt.rn.f16x2.f32 %0, %1, %2;" : "=r"(r) : "f"(po), "f"(pe));
    return r;
}
__device__ __forceinline__ void split2(float a, float b, uint32_t& hi, uint32_t& lo) {
    __nv_bfloat162 h = __floats2bfloat162_rn(a, b);
    float2 hf = __bfloat1622float2(h);
    __nv_bfloat162 l = __floats2bfloat162_rn(a - hf.x, b - hf.y);
    union { __nv_bfloat162 v; uint32_t u; } ch, cl;
    ch.v = h; cl.v = l;
    hi = ch.u; lo = cl.u;
}

#define LOG2E 1.4426950408889634f

// ====== QKV projection on HMMA bf16x3 (r15-proven version) ======
#define WHI_B 0
#define WLO_B 34816
#define XHI_B 69632
#define XLO_B 104448
#define PROJ_SMEM_BYTES 139264

__global__ void __launch_bounds__(256, 1) qkv_kernel(
    const float* __restrict__ x1, const float* __restrict__ x2,
    const float* __restrict__ Wq, const float* __restrict__ bq,
    const float* __restrict__ Wk, const float* __restrict__ bk,
    const float* __restrict__ Wv, const float* __restrict__ bv)
{
    extern __shared__ __align__(16) char smc[];
    const uint32_t sb = smem_u32(smc);

    const int t = threadIdx.x;
    const int wid = t >> 5;
    const int lane = t & 31;
    const int l7 = lane & 7;
    const int r8 = lane >> 3;
    const bool isQ = (blockIdx.y == 0);
    const int b = blockIdx.z, p0 = blockIdx.x * 128;

    const float* X = (isQ ? x1 : x2) + (size_t)b * CH * NPIX;

#pragma unroll
    for (int r = 0; r < 16; ++r) {
        int idx = t + 256 * r;
        int c = idx >> 5, p4 = (idx & 31) * 4;
        float4 x4 = *(const float4*)&X[(size_t)c * NPIX + p0 + p4];
        uint32_t h0, l0, h1, l1;
        split2(x4.x, x4.y, h0, l0);
        split2(x4.z, x4.w, h1, l1);
        *(uint2*)(smc + XHI_B + c * 272 + p4 * 2) = make_uint2(h0, h1);
        *(uint2*)(smc + XLO_B + c * 272 + p4 * 2) = make_uint2(l0, l1);
    }

    const int g = lane >> 2, q4 = lane & 3;
    const int npass = isQ ? 1 : 2;

    for (int pass = 0; pass < npass; ++pass) {
        const float* W    = isQ ? Wq : (pass == 0 ? Wk : Wv);
        const float* bias = isQ ? bq : (pass == 0 ? bk : bv);
        if (pass) __syncthreads();

#pragma unroll
        for (int r = 0; r < 4; ++r) {
            int task = t + 256 * r;
            int o = task >> 3, c16 = (task & 7) * 16;
            const float4* ws = (const float4*)&W[o * CH + c16];
            uint32_t hi[8], lo[8];
#pragma unroll
            for (int j = 0; j < 4; ++j) {
                float4 w4 = ws[j];
                split2(w4.x, w4.y, hi[2 * j], lo[2 * j]);
                split2(w4.z, w4.w, hi[2 * j + 1], lo[2 * j + 1]);
            }
            char* dh = smc + WHI_B + o * 272 + c16 * 2;
            char* dl = smc + WLO_B + o * 272 + c16 * 2;
            ((uint4*)dh)[0] = make_uint4(hi[0], hi[1], hi[2], hi[3]);
            ((uint4*)dh)[1] = make_uint4(hi[4], hi[5], hi[6], hi[7]);
            ((uint4*)dl)[0] = make_uint4(lo[0], lo[1], lo[2], lo[3]);
            ((uint4*)dl)[1] = make_uint4(lo[4], lo[5], lo[6], lo[7]);
        }
        __syncthreads();

        float acc[16][4];
#pragma unroll
        for (int n = 0; n < 16; ++n)
#pragma unroll
            for (int r = 0; r < 4; ++r) acc[n][r] = 0.f;

        if (isQ || pass == 0) {
            const uint32_t aT = sb + XHI_B
                + (uint32_t)((r8 & 1) * 8 + l7) * 272
                + (uint32_t)(wid * 16 + (r8 >> 1) * 8) * 2;
            const uint32_t bW = sb + WHI_B
                + (uint32_t)((r8 >> 1) * 8 + l7) * 272 + (uint32_t)(r8 & 1) * 16;
#pragma unroll
            for (int kk = 0; kk < 8; ++kk) {
                uint32_t a0h, a1h, a2h, a3h, a0l, a1l, a2l, a3l;
                ldsm4t(a0h, a2h, a1h, a3h, aT + kk * 16 * 272);
                ldsm4t(a0l, a2l, a1l, a3l, aT + (XLO_B - XHI_B) + kk * 16 * 272);
#pragma unroll
                for (int np = 0; np < 8; ++np) {
                    uint32_t b00, b01, b10, b11, c00, c01, c10, c11;
                    ldsm4(b00, b01, b10, b11, bW + np * 4352 + kk * 32);
                    ldsm4(c00, c01, c10, c11, bW + (WLO_B - WHI_B) + np * 4352 + kk * 32);
                    mma16816(acc[2 * np],     a0h, a1h, a2h, a3h, b00, b01);
                    mma16816(acc[2 * np],     a0l, a1l, a2l, a3l, b00, b01);
                    mma16816(acc[2 * np],     a0h, a1h, a2h, a3h, c00, c01);
                    mma16816(acc[2 * np + 1], a0h, a1h, a2h, a3h, b10, b11);
                    mma16816(acc[2 * np + 1], a0l, a1l, a2l, a3l, b10, b11);
                    mma16816(acc[2 * np + 1], a0h, a1h, a2h, a3h, c10, c11);
                }
            }
            const float qsc = isQ ? LOG2E : 1.0f;
            __nv_bfloat16* dHi = isQ ? g_Qhi : g_Khi;
            __nv_bfloat16* dLo = isQ ? g_Qlo : g_Klo;
            const int p = wid * 16 + g;
            size_t r0 = ((size_t)b * NPIX + p0 + p) * CH;
            size_t r8b = r0 + (size_t)8 * CH;
#pragma unroll
            for (int n = 0; n < 16; ++n) {
                const int o = n * 8 + 2 * q4;
                float2 bo = *(const float2*)&bias[o];
                uint32_t h0, l0, h1, l1;
                split2((acc[n][0] + bo.x) * qsc, (acc[n][1] + bo.y) * qsc, h0, l0);
                split2((acc[n][2] + bo.x) * qsc, (acc[n][3] + bo.y) * qsc, h1, l1);
                *(uint32_t*)(dHi + r0 + o)  = h0;
                *(uint32_t*)(dLo + r0 + o)  = l0;
                *(uint32_t*)(dHi + r8b + o) = h1;
                *(uint32_t*)(dLo + r8b + o) = l1;
            }
        } else {
            const uint32_t aH = sb + WHI_B
                + (uint32_t)(wid * 16 + l7 + (r8 & 1) * 8) * 272
                + (uint32_t)((lane >> 4) & 1) * 16;
            const uint32_t aL = aH + (WLO_B - WHI_B);
            const uint32_t bT = sb + XHI_B
                + (uint32_t)((r8 & 1) * 8 + l7) * 272 + (uint32_t)(r8 >> 1) * 16;
#pragma unroll
            for (int kk = 0; kk < 8; ++kk) {
                uint32_t a0h, a1h, a2h, a3h, a0l, a1l, a2l, a3l;
                ldsm4(a0h, a1h, a2h, a3h, aH + kk * 32);
                ldsm4(a0l, a1l, a2l, a3l, aL + kk * 32);
                const uint32_t bk16 = bT + (uint32_t)kk * 16 * 272;
#pragma unroll
                for (int np = 0; np < 8; ++np) {
                    uint32_t b00, b01, b10, b11, c00, c01, c10, c11;
                    ldsm4t(b00, b01, b10, b11, bk16 + np * 32);
                    ldsm4t(c00, c01, c10, c11, bk16 + (XLO_B - XHI_B) + np * 32);
                    mma16816(acc[2 * np],     a0h, a1h, a2h, a3h, b00, b01);
                    mma16816(acc[2 * np],     a0l, a1l, a2l, a3l, b00, b01);
                    mma16816(acc[2 * np],     a0h, a1h, a2h, a3h, c00, c01);
                    mma16816(acc[2 * np + 1], a0h, a1h, a2h, a3h, b10, b11);
                    mma16816(acc[2 * np + 1], a0l, a1l, a2l, a3l, b10, b11);
                    mma16816(acc[2 * np + 1], a0h, a1h, a2h, a3h, c10, c11);
                }
            }
            const int o0 = wid * 16 + g;
            float bo0 = bv[o0], bo8 = bv[o0 + 8];
            size_t rb0 = ((size_t)b * CH + o0) * NPIX + p0;
            size_t rb8 = rb0 + (size_t)8 * NPIX;
#pragma unroll
            for (int n = 0; n < 16; ++n) {
                const int p = n * 8 + 2 * q4;
                *(uint32_t*)(g_Vh + rb0 + p) = f16pack(acc[n][0] + bo0, acc[n][1] + bo0);
                *(uint32_t*)(g_Vh + rb8 + p) = f16pack(acc[n][2] + bo8, acc[n][3] + bo8);
            }
        }
    }
}

// ==== flash attention partial: bf16x3 S + fp16 PV, running row-max (r15) ====
#define QHI_B 0
#define QLO_B 34816
#define BUF_B 69632
#define BUFSTRIDE 53248   // Khi 17408 + Klo 17408 + Vh 18432
#define KHI_B(d) (BUF_B + (d) * BUFSTRIDE)
#define VH_B(d)  (KHI_B(d) + 2 * 17408)
#define ATTN_SMEM_BYTES (BUF_B + 2 * BUFSTRIDE)   // 176128

__global__ void __launch_bounds__(256, 1) attn_kernel()
{
    extern __shared__ __align__(16) uint32_t sm32[];
    const uint32_t sb = smem_u32(sm32);

    const int t = threadIdx.x;
    const int wid = t >> 5;
    const int lane = t & 31;
    const int l7 = lane & 7;
    const int r8 = lane >> 3;
    const int iblk = blockIdx.x;
    const int jc   = blockIdx.y;
    const int b    = blockIdx.z;
    const int i0 = iblk * BR;
    const int jt0 = jc * TILES_PER_UNIT;

    {
        const char* qh = (const char*)(g_Qhi + ((size_t)b * NPIX + i0) * CH);
        const char* ql = (const char*)(g_Qlo + ((size_t)b * NPIX + i0) * CH);
#pragma unroll
        for (int r = 0; r < 8; ++r) {
            int idx = t + 256 * r;
            int row = idx >> 4, off = idx & 15;
            cpasync16(sb + QHI_B + row * 272 + off * 16, qh + (size_t)idx * 16);
            cpasync16(sb + QLO_B + row * 272 + off * 16, ql + (size_t)idx * 16);
        }
        const int j0 = jt0 * BC;
        const char* kh = (const char*)(g_Khi + ((size_t)b * NPIX + j0) * CH);
        const char* kl = (const char*)(g_Klo + ((size_t)b * NPIX + j0) * CH);
        const char* vh = (const char*)(g_Vh + (size_t)b * CH * NPIX + j0);
#pragma unroll
        for (int r = 0; r < 4; ++r) {
            int idx = t + 256 * r;
            int row = idx >> 4, off = idx & 15;
            cpasync16(sb + KHI_B(0) + row * 272 + off * 16, kh + (size_t)idx * 16);
            cpasync16(sb + KHI_B(0) + 17408 + row * 272 + off * 16, kl + (size_t)idx * 16);
        }
#pragma unroll
        for (int r = 0; r < 4; ++r) {
            int idx = t + 256 * r;
            int row = idx >> 3, off = idx & 7;
            cpasync16(sb + VH_B(0) + row * 144 + off * 16,
                      vh + (size_t)row * NPIX * 2 + off * 16);
        }
        CP_COMMIT();
    }

    float o[16][4];
#pragma unroll
    for (int n = 0; n < 16; ++n)
#pragma unroll
        for (int r = 0; r < 4; ++r) o[n][r] = 0.f;
    float lsum0 = 0.f, lsum1 = 0.f;
    float m0 = -INFINITY, m1 = -INFINITY;

    const uint32_t aOffH = sb + QHI_B
        + (uint32_t)(wid * 16 + l7 + (r8 & 1) * 8) * 272 + (uint32_t)((lane >> 4) & 1) * 16;
    const uint32_t aOffL = aOffH + (QLO_B - QHI_B);
    const uint32_t bRow = (uint32_t)((r8 >> 1) * 8 + l7);
    const uint32_t bOffK = bRow * 272 + (uint32_t)(r8 & 1) * 16;
    const uint32_t bOffV = bRow * 144 + (uint32_t)(r8 & 1) * 16;

    for (int jt = jt0; jt < jt0 + TILES_PER_UNIT; ++jt) {
        const int d = jt & 1;
        CP_WAIT0();
        __syncthreads();

        if (jt + 1 < jt0 + TILES_PER_UNIT) {
            const int j0n = (jt + 1) * BC, dn = (jt + 1) & 1;
            const char* kh = (const char*)(g_Khi + ((size_t)b * NPIX + j0n) * CH);
            const char* kl = (const char*)(g_Klo + ((size_t)b * NPIX + j0n) * CH);
            const char* vh = (const char*)(g_Vh + (size_t)b * CH * NPIX + j0n);
#pragma unroll
            for (int r = 0; r < 4; ++r) {
                int idx = t + 256 * r;
                int row = idx >> 4, off = idx & 15;
                cpasync16(sb + KHI_B(dn) + row * 272 + off * 16, kh + (size_t)idx * 16);
                cpasync16(sb + KHI_B(dn) + 17408 + row * 272 + off * 16, kl + (size_t)idx * 16);
            }
#pragma unroll
            for (int r = 0; r < 4; ++r) {
                int idx = t + 256 * r;
                int row = idx >> 3, off = idx & 7;
                cpasync16(sb + VH_B(dn) + row * 144 + off * 16,
                          vh + (size_t)row * NPIX * 2 + off * 16);
            }
            CP_COMMIT();
        }

        // ---- S = Q K^T (3-term bf16) ----
        float s[8][4];
#pragma unroll
        for (int n = 0; n < 8; ++n)
#pragma unroll
            for (int r = 0; r < 4; ++r) s[n][r] = 0.f;

        const uint32_t kBase = sb + KHI_B(d) + bOffK;
#pragma unroll
        for (int kk = 0; kk < 8; ++kk) {
            uint32_t a0h, a1h, a2h, a3h, a0l, a1l, a2l, a3l;
            ldsm4(a0h, a1h, a2h, a3h, aOffH + kk * 32);
            ldsm4(a0l, a1l, a2l, a3l, aOffL + kk * 32);
#pragma unroll
            for (int np = 0; np < 4; ++np) {
                uint32_t b00, b01, b10, b11, c00, c01, c10, c11;
                ldsm4(b00, b01, b10, b11, kBase + np * 4352 + kk * 32);
                ldsm4(c00, c01, c10, c11, kBase + 17408 + np * 4352 + kk * 32);
                mma16816(s[2 * np],     a0h, a1h, a2h, a3h, b00, b01);
                mma16816(s[2 * np],     a0l, a1l, a2l, a3l, b00, b01);
                mma16816(s[2 * np],     a0h, a1h, a2h, a3h, c00, c01);
                mma16816(s[2 * np + 1], a0h, a1h, a2h, a3h, b10, b11);
                mma16816(s[2 * np + 1], a0l, a1l, a2l, a3l, b10, b11);
                mma16816(s[2 * np + 1], a0h, a1h, a2h, a3h, c10, c11);
            }
        }

        // ---- running row-max, unconditional rescale, exp2, sums ----
        {
            float mx0 = s[0][0], mx1 = s[0][2];
#pragma unroll
            for (int n = 0; n < 8; ++n) {
                mx0 = fmaxf(mx0, fmaxf(s[n][0], s[n][1]));
                mx1 = fmaxf(mx1, fmaxf(s[n][2], s[n][3]));
            }
            mx0 = fmaxf(mx0, __shfl_xor_sync(0xffffffffu, mx0, 1));
            mx0 = fmaxf(mx0, __shfl_xor_sync(0xffffffffu, mx0, 2));
            mx1 = fmaxf(mx1, __shfl_xor_sync(0xffffffffu, mx1, 1));
            mx1 = fmaxf(mx1, __shfl_xor_sync(0xffffffffu, mx1, 2));
            float m0n = fmaxf(m0, mx0), m1n = fmaxf(m1, mx1);
            float sc0 = ex2(m0 - m0n), sc1 = ex2(m1 - m1n);
            m0 = m0n; m1 = m1n;
            lsum0 *= sc0; lsum1 *= sc1;
#pragma unroll
            for (int n = 0; n < 8; ++n) {
                s[n][0] = ex2(s[n][0] - m0n);
                s[n][1] = ex2(s[n][1] - m0n);
                s[n][2] = ex2(s[n][2] - m1n);
                s[n][3] = ex2(s[n][3] - m1n);
                lsum0 += s[n][0] + s[n][1];
                lsum1 += s[n][2] + s[n][3];
            }
#pragma unroll
            for (int n = 0; n < 16; ++n) {
                o[n][0] *= sc0; o[n][1] *= sc0;
                o[n][2] *= sc1; o[n][3] *= sc1;
            }
        }

        // ---- O += P V : single-term fp16 ----
        const uint32_t vBase = sb + VH_B(d) + bOffV;
#pragma unroll
        for (int kk = 0; kk < 4; ++kk) {
            uint32_t pa0 = f16pack(s[2 * kk][0],     s[2 * kk][1]);
            uint32_t pa1 = f16pack(s[2 * kk][2],     s[2 * kk][3]);
            uint32_t pa2 = f16pack(s[2 * kk + 1][0], s[2 * kk + 1][1]);
            uint32_t pa3 = f16pack(s[2 * kk + 1][2], s[2 * kk + 1][3]);
#pragma unroll
            for (int n2 = 0; n2 < 8; ++n2) {
                uint32_t b00, b01, b10, b11;
                ldsm4(b00, b01, b10, b11, vBase + n2 * 2304 + kk * 32);
                mma16816h(o[2 * n2],     pa0, pa1, pa2, pa3, b00, b01);
                mma16816h(o[2 * n2 + 1], pa0, pa1, pa2, pa3, b10, b11);
            }
        }
        __syncthreads();
    }

    lsum0 += __shfl_xor_sync(0xffffffffu, lsum0, 1);
    lsum0 += __shfl_xor_sync(0xffffffffu, lsum0, 2);
    lsum1 += __shfl_xor_sync(0xffffffffu, lsum1, 1);
    lsum1 += __shfl_xor_sync(0xffffffffu, lsum1, 2);

    const size_t unit = ((size_t)(b * JSPLIT + jc) * 32 + iblk);
    float* Ob = g_O + unit * (128 * 128);
    float* ML = g_ML + unit * 256;
    const int g = lane >> 2, q = lane & 3;
    const int i = wid * 16 + g;
    if ((lane & 3) == 0) {
        ML[i]           = m0;
        ML[i + 8]       = m1;
        ML[128 + i]     = lsum0;
        ML[128 + i + 8] = lsum1;
    }
#pragma unroll
    for (int n = 0; n < 16; ++n) {
        const int c = n * 8 + 2 * q;
        *(float2*)&Ob[(size_t)i * 128 + c]       = make_float2(o[n][0], o[n][1]);
        *(float2*)&Ob[(size_t)(i + 8) * 128 + c] = make_float2(o[n][2], o[n][3]);
    }
}

// ==== merge: max-combine 4 j-chunk partials; split over i-halves ====
// grid (32, 2, 8): blockIdx.y = i-half
#define MERGE_SMEM_BYTES (128 * 65 * 4 + 64 * 4 + 4 * 64 * 4)   // 34560

__global__ void __launch_bounds__(256, 1) merge_kernel(float* __restrict__ out)
{
    extern __shared__ __align__(16) float ms[];
    float* Os   = ms;                      // [c:128][i:65]
    float* Linv = ms + 128 * 65;           // [64]
    float* F    = ms + 128 * 65 + 64;      // [4][64]

    const int t = threadIdx.x;
    const int iblk = blockIdx.x;
    const int ih   = blockIdx.y;
    const int b    = blockIdx.z;

    const float* O0 = g_O + ((size_t)(b * JSPLIT) * 32 + iblk) * (128 * 128);
    const size_t sj = (size_t)32 * 128 * 128;

    if (t < 64) {
        const int i = ih * 64 + t;
        const size_t u0 = ((size_t)(b * JSPLIT) * 32 + iblk) * 256;
        const size_t uj = (size_t)32 * 256;
        float m[4], l[4];
#pragma unroll
        for (int c = 0; c < 4; ++c) {
            m[c] = g_ML[u0 + c * uj + i];
            l[c] = g_ML[u0 + c * uj + 128 + i];
        }
        float M = fmaxf(fmaxf(m[0], m[1]), fmaxf(m[2], m[3]));
        float L = 0.f;
#pragma unroll
        for (int c = 0; c < 4; ++c) {
            float f = ex2(m[c] - M);
            F[c * 64 + t] = f;
            L += l[c] * f;
        }
        Linv[t] = 1.f / L;
    }
    __syncthreads();

#pragma unroll
    for (int r = 0; r < 8; ++r) {
        int lin = (r * 256 + t) * 4;             // 8192 floats = 64 i x 128 c
        int il = lin >> 7, c = lin & 127;
        size_t idx = (size_t)(ih * 64 + il) * 128 + c;
        float f0 = F[il], f1 = F[64 + il], f2 = F[128 + il], f3 = F[192 + il];
        float4 a  = *(const float4*)&O0[idx];
        float4 b2 = *(const float4*)&O0[sj + idx];
        float4 c4 = *(const float4*)&O0[2 * sj + idx];
        float4 d4 = *(const float4*)&O0[3 * sj + idx];
        Os[(c + 0) * 65 + il] = a.x * f0 + b2.x * f1 + c4.x * f2 + d4.x * f3;
        Os[(c + 1) * 65 + il] = a.y * f0 + b2.y * f1 + c4.y * f2 + d4.y * f3;
        Os[(c + 2) * 65 + il] = a.z * f0 + b2.z * f1 + c4.z * f2 + d4.z * f3;
        Os[(c + 3) * 65 + il] = a.w * f0 + b2.w * f1 + c4.w * f2 + d4.w * f3;
    }
    __syncthreads();

    const int c = t >> 1, h = t & 1;
    const float* src = Os + c * 65 + 32 * h;
    const float* li  = Linv + 32 * h;
    float* dst = out + ((size_t)b * CH + c) * NPIX + iblk * 128 + ih * 64 + 32 * h;
#pragma unroll
    for (int k = 0; k < 8; ++k) {
        ((float4*)dst)[k] = make_float4(src[4 * k]     * li[4 * k],
                                        src[4 * k + 1] * li[4 * k + 1],
                                        src[4 * k + 2] * li[4 * k + 2],
                                        src[4 * k + 3] * li[4 * k + 3]);
    }
}

// ============================================================
extern "C" void kernel_launch(void* const* d_in, const int* in_sizes, int n_in,
                              void* d_out, int out_size)
{
    (void)in_sizes; (void)n_in; (void)out_size;
    const float* x1 = (const float*)d_in[0];
    const float* x2 = (const float*)d_in[1];
    const float* Wq = (const float*)d_in[2];
    const float* bq = (const float*)d_in[3];
    const float* Wk = (const float*)d_in[4];
    const float* bk = (const float*)d_in[5];
    const float* Wv = (const float*)d_in[6];
    const float* bv = (const float*)d_in[7];
    float* out = (float*)d_out;

    cudaFuncSetAttribute(qkv_kernel, cudaFuncAttributeMaxDynamicSharedMemorySize, PROJ_SMEM_BYTES);
    cudaFuncSetAttribute(attn_kernel, cudaFuncAttributeMaxDynamicSharedMemorySize, ATTN_SMEM_BYTES);
    cudaFuncSetAttribute(merge_kernel, cudaFuncAttributeMaxDynamicSharedMemorySize, MERGE_SMEM_BYTES);

    qkv_kernel<<<dim3(NPIX / 128, 2, BATCH), 256, PROJ_SMEM_BYTES>>>(x1, x2, Wq, bq, Wk, bk, Wv, bv);
    attn_kernel<<<dim3(NPIX / BR, JSPLIT, BATCH), 256, ATTN_SMEM_BYTES>>>();
    merge_kernel<<<dim3(NPIX / 128, 2, BATCH), 256, MERGE_SMEM_BYTES>>>(out);
}